// round 13
// baseline (speedup 1.0000x reference)
#include <cuda_runtime.h>
#include <math.h>

// EpochedFutureFill: B=256, T=32768, L=32768 -> n_fft = 65536 = 256*256.
// Four-step FFT convolution, register-resident 256-pt warp FFTs.
// R13: mid-FFT per-warp smem re-layout: shfl stages 5 -> 2.
//   Phase A (p = 32k+lane): intra d=128,64,32
//   swap (reuses tile rows, pad-36 conflict-free)
//   Phase B (p = 32b+o+4j, b=lane>>2, o=lane&3): intra d=16,8,4; shfl d=2,1
// d=1 has W=1: no multiply. Long twiddle tables (R11) unchanged.
#define T_LEN   32768
#define N_FFT   65536
#define NSIG    128
#define SCALE_INV (1.0f / 65536.0f)
#define ROWW    284   // scratch/tile row length (max swap idx 283)

__device__ float4 d_scr4[NSIG * N_FFT / 2];  // 64 MB workspace (16B aligned)
__device__ float2 d_Htmp[N_FFT];             // filter intermediate
__device__ float2 d_Hs[N_FFT];               // filter spectrum [p][q] slots
__device__ float2 d_t256g[256];              // W_256^j
__device__ float2 d_WL [N_FFT];              // W_N^{n1*brev(p)}, [n1][p]
__device__ float2 d_WLT[N_FFT];              // same values, [p][n1]

__device__ __forceinline__ float2 cmul(float2 a, float2 b) {
    return make_float2(a.x * b.x - a.y * b.y, a.x * b.y + a.y * b.x);
}
__device__ __forceinline__ float2 cmulc(float2 a, float2 b) {  // a * conj(b)
    return make_float2(a.x * b.x + a.y * b.y, a.y * b.x - a.x * b.y);
}
__device__ __forceinline__ void bfly_f(float2& lo, float2& hi, float2 w) {
    float2 a = lo, b = hi;
    lo = make_float2(a.x + b.x, a.y + b.y);
    hi = cmul(make_float2(a.x - b.x, a.y - b.y), w);
}
__device__ __forceinline__ void bfly_i(float2& lo, float2& hi, float2 w) {
    float2 t = cmulc(hi, w);
    float2 a = lo;
    lo = make_float2(a.x + t.x, a.y + t.y);
    hi = make_float2(a.x - t.x, a.y - t.y);
}

// One-time twiddle build: t256 + both long-twiddle tables.
__global__ void k_init() {
    int idx = blockIdx.x * 256 + threadIdx.x;    // 256 x 256 = 65536
    int n1 = idx >> 8, p = idx & 255;
    int k2 = __brev(p) >> 24;
    float sn, cs;
    sincospif(-(float)(n1 * k2) / 32768.0f, &sn, &cs);
    float2 wv = make_float2(cs, sn);
    d_WL [idx]          = wv;
    d_WLT[p * 256 + n1] = wv;
    if (idx < 256) {
        sincospif(-(float)idx / 128.0f, &sn, &cs);
        d_t256g[idx] = make_float2(cs, sn);
    }
}

// ---- forward 256-pt FFT: A-layout in, B-layout out (slots preserved) ----
__device__ __forceinline__ void fft256_fwd(float2 v[8],
                                           const float2* __restrict__ t256,
                                           float* __restrict__ swr,
                                           float* __restrict__ swi, int lane) {
    // A: d=128
#pragma unroll
    for (int k = 0; k < 4; ++k) bfly_f(v[k], v[k + 4], t256[32 * k + lane]);
    {   // A: d=64
        float2 w0 = t256[2 * lane], w1 = t256[64 + 2 * lane];
        bfly_f(v[0], v[2], w0); bfly_f(v[1], v[3], w1);
        bfly_f(v[4], v[6], w0); bfly_f(v[5], v[7], w1);
    }
    {   // A: d=32
        float2 w = t256[4 * lane];
        bfly_f(v[0], v[1], w); bfly_f(v[2], v[3], w);
        bfly_f(v[4], v[5], w); bfly_f(v[6], v[7], w);
    }
    // swap A -> B
    __syncwarp();
#pragma unroll
    for (int k = 0; k < 8; ++k) {
        swr[36 * k + lane] = v[k].x;  swi[36 * k + lane] = v[k].y;
    }
    __syncwarp();
    const int o = lane & 3, bs = 36 * (lane >> 2) + o;
#pragma unroll
    for (int j = 0; j < 8; ++j)
        v[j] = make_float2(swr[bs + 4 * j], swi[bs + 4 * j]);
    __syncwarp();
    // B: d=16  pairs (j, j+4), w = W_256^{8(o+4j)}
#pragma unroll
    for (int j = 0; j < 4; ++j) bfly_f(v[j], v[j + 4], t256[8 * o + 32 * j]);
    {   // B: d=8  pairs (0,2)(1,3)(4,6)(5,7), w = W_256^{16(o+4(j&1))}
        float2 w0 = t256[16 * o], w1 = t256[16 * o + 64];
        bfly_f(v[0], v[2], w0); bfly_f(v[1], v[3], w1);
        bfly_f(v[4], v[6], w0); bfly_f(v[5], v[7], w1);
    }
    {   // B: d=4  pairs (k,k+1), w = W_256^{32o}
        float2 w = t256[32 * o];
        bfly_f(v[0], v[1], w); bfly_f(v[2], v[3], w);
        bfly_f(v[4], v[5], w); bfly_f(v[6], v[7], w);
    }
    {   // shfl d=2: w = W_256^{64(o&1)}; up = o&2
        float2 w = t256[64 * (o & 1)];
        const bool up = (o & 2) != 0;
#pragma unroll
        for (int k = 0; k < 8; ++k) {
            float tr = __shfl_xor_sync(0xffffffffu, v[k].x, 2);
            float ti = __shfl_xor_sync(0xffffffffu, v[k].y, 2);
            if (up) v[k] = cmul(make_float2(tr - v[k].x, ti - v[k].y), w);
            else    { v[k].x += tr; v[k].y += ti; }
        }
    }
    {   // shfl d=1: w = 1 (no multiply); up = o&1
        const bool up = (o & 1) != 0;
#pragma unroll
        for (int k = 0; k < 8; ++k) {
            float tr = __shfl_xor_sync(0xffffffffu, v[k].x, 1);
            float ti = __shfl_xor_sync(0xffffffffu, v[k].y, 1);
            v[k] = up ? make_float2(tr - v[k].x, ti - v[k].y)
                      : make_float2(v[k].x + tr, v[k].y + ti);
        }
    }
}

// ---- inverse 256-pt FFT (unnormalized x256): B-layout in, A-layout out ----
__device__ __forceinline__ void fft256_inv(float2 v[8],
                                           const float2* __restrict__ t256,
                                           float* __restrict__ swr,
                                           float* __restrict__ swi, int lane) {
    const int o = lane & 3;
    {   // shfl d=1 (w = 1): t = hi; (lo+t, lo-t)
        const bool up = (o & 1) != 0;
#pragma unroll
        for (int k = 0; k < 8; ++k) {
            float tr = __shfl_xor_sync(0xffffffffu, v[k].x, 1);
            float ti = __shfl_xor_sync(0xffffffffu, v[k].y, 1);
            v[k] = up ? make_float2(tr - v[k].x, ti - v[k].y)
                      : make_float2(v[k].x + tr, v[k].y + ti);
        }
    }
    {   // shfl d=2: conj twiddle on up lanes before exchange
        float2 w = t256[64 * (o & 1)];
        const bool up = (o & 2) != 0;
#pragma unroll
        for (int k = 0; k < 8; ++k) {
            float2 x = v[k];
            if (up) x = cmulc(x, w);
            float tr = __shfl_xor_sync(0xffffffffu, x.x, 2);
            float ti = __shfl_xor_sync(0xffffffffu, x.y, 2);
            v[k] = up ? make_float2(tr - x.x, ti - x.y)
                      : make_float2(x.x + tr, x.y + ti);
        }
    }
    {   // B: d=4
        float2 w = t256[32 * o];
        bfly_i(v[0], v[1], w); bfly_i(v[2], v[3], w);
        bfly_i(v[4], v[5], w); bfly_i(v[6], v[7], w);
    }
    {   // B: d=8
        float2 w0 = t256[16 * o], w1 = t256[16 * o + 64];
        bfly_i(v[0], v[2], w0); bfly_i(v[1], v[3], w1);
        bfly_i(v[4], v[6], w0); bfly_i(v[5], v[7], w1);
    }
    // B: d=16
#pragma unroll
    for (int j = 0; j < 4; ++j) bfly_i(v[j], v[j + 4], t256[8 * o + 32 * j]);
    // swap B -> A
    __syncwarp();
    {
        const int bs = 36 * (lane >> 2) + o;
#pragma unroll
        for (int j = 0; j < 8; ++j) {
            swr[bs + 4 * j] = v[j].x;  swi[bs + 4 * j] = v[j].y;
        }
    }
    __syncwarp();
#pragma unroll
    for (int k = 0; k < 8; ++k)
        v[k] = make_float2(swr[36 * k + lane], swi[36 * k + lane]);
    __syncwarp();
    {   // A: d=32
        float2 w = t256[4 * lane];
        bfly_i(v[0], v[1], w); bfly_i(v[2], v[3], w);
        bfly_i(v[4], v[5], w); bfly_i(v[6], v[7], w);
    }
    {   // A: d=64
        float2 w0 = t256[2 * lane], w1 = t256[64 + 2 * lane];
        bfly_i(v[0], v[2], w0); bfly_i(v[1], v[3], w1);
        bfly_i(v[4], v[6], w0); bfly_i(v[5], v[7], w1);
    }
    // A: d=128
#pragma unroll
    for (int k = 0; k < 4; ++k) bfly_i(v[k], v[k + 4], t256[32 * k + lane]);
}

// ---------------------------------------------------------------------------
// Pass 1: FFT over n2, long twiddle (d_WL row), store d_scr slots.
// ---------------------------------------------------------------------------
__global__ void __launch_bounds__(256, 3) k_pass1(const float* __restrict__ x) {
    __shared__ float  sre[8][ROWW], sim[8][ROWW];
    __shared__ float2 t256[256];
    const int tid = threadIdx.x, sgn = blockIdx.y, n1b = blockIdx.x * 8;
    t256[tid] = d_t256g[tid];

    const float4* __restrict__ xr4 =
        (const float4*)(x + (size_t)(2 * sgn)     * T_LEN);
    const float4* __restrict__ xi4 =
        (const float4*)(x + (size_t)(2 * sgn + 1) * T_LEN);
    {
        int n1q = tid & 1, n2 = tid >> 1;
        int g4 = (n1b >> 2) + n1q + 64 * n2;   // float4 index
        float4 a = xr4[g4];
        sre[4*n1q+0][n2] = a.x; sre[4*n1q+1][n2] = a.y;
        sre[4*n1q+2][n2] = a.z; sre[4*n1q+3][n2] = a.w;
        float4 b = xi4[g4];
        sim[4*n1q+0][n2] = b.x; sim[4*n1q+1][n2] = b.y;
        sim[4*n1q+2][n2] = b.z; sim[4*n1q+3][n2] = b.w;
    }
    __syncthreads();

    const int w = tid >> 5, lane = tid & 31;
    float2 v[8];
#pragma unroll
    for (int k = 0; k < 4; ++k) {
        v[k]     = make_float2(sre[w][32 * k + lane], sim[w][32 * k + lane]);
        v[k + 4] = make_float2(0.f, 0.f);      // zero pad [T, N)
    }
    fft256_fwd(v, t256, sre[w], sim[w], lane);  // ends in B layout

    const int n1 = n1b + w;
    const int pb0 = 32 * (lane >> 2) + (lane & 3);
    const float2* __restrict__ WL = d_WL + (size_t)n1 * 256;
    float2* __restrict__ out =
        (float2*)d_scr4 + (size_t)sgn * N_FFT + (size_t)n1 * 256;
#pragma unroll
    for (int j = 0; j < 8; ++j) {
        int p = pb0 + 4 * j;
        out[p] = cmul(v[j], WL[p]);            // 32B-sector chunks
    }
}

// ---------------------------------------------------------------------------
// Pass 2 (fused): fwd FFT over n1, multiply Hs, inverse FFT, un-twiddle.
// ---------------------------------------------------------------------------
__global__ void __launch_bounds__(256, 3) k_pass2() {
    __shared__ float  sre[8][ROWW], sim[8][ROWW];
    __shared__ float2 t256[256];
    const int tid = threadIdx.x, sgn = blockIdx.y, pb = blockIdx.x * 8;
    t256[tid] = d_t256g[tid];

    float2* __restrict__ base = (float2*)d_scr4 + (size_t)sgn * N_FFT;
#pragma unroll
    for (int it = 0; it < 4; ++it) {
        int idx = tid + it * 256;
        int jj = idx & 3, n1 = idx >> 2;
        float4 t = *(const float4*)&base[(size_t)n1 * 256 + pb + 2 * jj];
        sre[2*jj  ][n1] = t.x;  sim[2*jj  ][n1] = t.y;
        sre[2*jj+1][n1] = t.z;  sim[2*jj+1][n1] = t.w;
    }
    __syncthreads();

    const int w = tid >> 5, lane = tid & 31;
    float2 v[8];
#pragma unroll
    for (int k = 0; k < 8; ++k)
        v[k] = make_float2(sre[w][32 * k + lane], sim[w][32 * k + lane]);
    // row w fully consumed by warp w; scratch use below is warp-private.

    fft256_fwd(v, t256, sre[w], sim[w], lane);  // over n1 -> slots q (B layout)

    const int p = pb + w;
    const int qb0 = 32 * (lane >> 2) + (lane & 3);
    const float2* __restrict__ H = d_Hs + (size_t)p * 256;
#pragma unroll
    for (int j = 0; j < 8; ++j) v[j] = cmul(v[j], H[qb0 + 4 * j]);

    fft256_inv(v, t256, sre[w], sim[w], lane);  // -> natural n1 (A layout)

    const float2* __restrict__ WT = d_WLT + (size_t)p * 256;
#pragma unroll
    for (int k = 0; k < 8; ++k) {
        int n1 = 32 * k + lane;
        v[k] = cmulc(v[k], WT[n1]);            // * W_N^{-n1*k2}
    }

    __syncthreads();                           // all warps done with scratch
#pragma unroll
    for (int k = 0; k < 8; ++k) {
        sre[w][32 * k + lane] = v[k].x;
        sim[w][32 * k + lane] = v[k].y;
    }
    __syncthreads();
#pragma unroll
    for (int it = 0; it < 4; ++it) {
        int idx = tid + it * 256;
        int jj = idx & 3, n1 = idx >> 2;
        float4 t;
        t.x = sre[2*jj  ][n1];  t.y = sim[2*jj  ][n1];
        t.z = sre[2*jj+1][n1];  t.w = sim[2*jj+1][n1];
        *(float4*)&base[(size_t)n1 * 256 + pb + 2 * jj] = t;
    }
}

// ---------------------------------------------------------------------------
// Pass 3: inverse FFT over k2 (B-layout gather), scale, transposed store.
// ---------------------------------------------------------------------------
__global__ void __launch_bounds__(256, 3) k_pass3(float* __restrict__ y) {
    __shared__ float  sre[8][ROWW], sim[8][ROWW];
    __shared__ float2 t256[256];
    const int tid = threadIdx.x, sgn = blockIdx.y, n1b = blockIdx.x * 8;
    t256[tid] = d_t256g[tid];

    const int w = tid >> 5, lane = tid & 31;
    const float2* __restrict__ row =
        (float2*)d_scr4 + (size_t)sgn * N_FFT + (size_t)(n1b + w) * 256;
    const int pb0 = 32 * (lane >> 2) + (lane & 3);
    float2 v[8];
#pragma unroll
    for (int j = 0; j < 8; ++j) v[j] = row[pb0 + 4 * j];   // 32B chunks
    __syncthreads();                           // t256 ready

    fft256_inv(v, t256, sre[w], sim[w], lane); // natural n2 = 32k+lane

    __syncthreads();                           // scratch free before tile use
#pragma unroll
    for (int k = 0; k < 4; ++k) {              // only n2 < 128 -> n < T
        sre[w][32 * k + lane] = v[k].x * SCALE_INV;
        sim[w][32 * k + lane] = v[k].y * SCALE_INV;
    }
    __syncthreads();

    float4* __restrict__ yr4 = (float4*)(y + (size_t)(2 * sgn)     * T_LEN);
    float4* __restrict__ yi4 = (float4*)(y + (size_t)(2 * sgn + 1) * T_LEN);
    {
        int n1q = tid & 1, n2 = tid >> 1;
        int g4 = (n1b >> 2) + n1q + 64 * n2;
        float4 a, b;
        a.x = sre[4*n1q+0][n2]; a.y = sre[4*n1q+1][n2];
        a.z = sre[4*n1q+2][n2]; a.w = sre[4*n1q+3][n2];
        b.x = sim[4*n1q+0][n2]; b.y = sim[4*n1q+1][n2];
        b.z = sim[4*n1q+2][n2]; b.w = sim[4*n1q+3][n2];
        yr4[g4] = a;
        yi4[g4] = b;
    }
}

// ---------------------------------------------------------------------------
// Filter pass 1: real input -> d_Htmp slots [n1][p].
// ---------------------------------------------------------------------------
__global__ void __launch_bounds__(256) k_fpass1(const float* __restrict__ filt) {
    __shared__ float  sre[8][ROWW], sim[8][ROWW];
    __shared__ float2 t256[256];
    const int tid = threadIdx.x, n1b = blockIdx.x * 8;
    t256[tid] = d_t256g[tid];

#pragma unroll
    for (int it = 0; it < 4; ++it) {
        int idx = tid + it * 256;
        int n1l = idx & 7, n2 = idx >> 3;
        sre[n1l][n2] = filt[n1b + n1l + 256 * n2];   // < 32768 = L
    }
    __syncthreads();

    const int w = tid >> 5, lane = tid & 31;
    float2 v[8];
#pragma unroll
    for (int k = 0; k < 4; ++k) {
        v[k]     = make_float2(sre[w][32 * k + lane], 0.f);
        v[k + 4] = make_float2(0.f, 0.f);
    }
    fft256_fwd(v, t256, sre[w], sim[w], lane);

    const int n1 = n1b + w;
    const int pb0 = 32 * (lane >> 2) + (lane & 3);
    const float2* __restrict__ WL = d_WL + (size_t)n1 * 256;
    float2* __restrict__ out = d_Htmp + (size_t)n1 * 256;
#pragma unroll
    for (int j = 0; j < 8; ++j) {
        int p = pb0 + 4 * j;
        out[p] = cmul(v[j], WL[p]);
    }
}

// ---------------------------------------------------------------------------
// Filter pass 2: fwd FFT over n1 per p; store slots d_Hs[p*256 + q].
// ---------------------------------------------------------------------------
__global__ void __launch_bounds__(256) k_fpass2() {
    __shared__ float  sre[8][ROWW], sim[8][ROWW];
    __shared__ float2 t256[256];
    const int tid = threadIdx.x, pb = blockIdx.x * 8;
    t256[tid] = d_t256g[tid];

#pragma unroll
    for (int it = 0; it < 8; ++it) {
        int idx = tid + it * 256;
        int j = idx & 7, n1 = idx >> 3;
        float2 t = d_Htmp[(size_t)n1 * 256 + pb + j];
        sre[j][n1] = t.x;  sim[j][n1] = t.y;
    }
    __syncthreads();

    const int w = tid >> 5, lane = tid & 31;
    float2 v[8];
#pragma unroll
    for (int k = 0; k < 8; ++k)
        v[k] = make_float2(sre[w][32 * k + lane], sim[w][32 * k + lane]);
    fft256_fwd(v, t256, sre[w], sim[w], lane);  // ends B layout

    const int qb0 = 32 * (lane >> 2) + (lane & 3);
    float2* __restrict__ out = (float2*)d_Hs + (size_t)(pb + w) * 256;
#pragma unroll
    for (int j = 0; j < 8; ++j) out[qb0 + 4 * j] = v[j];
}

// ---------------------------------------------------------------------------
extern "C" void kernel_launch(void* const* d_in, const int* in_sizes, int n_in,
                              void* d_out, int out_size) {
    (void)out_size;
    const float* x    = (const float*)d_in[0];   // (256, 32768) fp32
    const float* filt = (const float*)d_in[1];   // (1, 32768)   fp32
    if (in_sizes && n_in >= 2 && in_sizes[0] == T_LEN) {  // safety: swapped
        x    = (const float*)d_in[1];
        filt = (const float*)d_in[0];
    }
    float* y = (float*)d_out;                    // (256, 32768) fp32

    k_init  <<<256, 256>>>();
    k_fpass1<<<32, 256>>>(filt);
    k_fpass2<<<32, 256>>>();
    k_pass1 <<<dim3(32, NSIG), 256>>>(x);
    k_pass2 <<<dim3(32, NSIG), 256>>>();
    k_pass3 <<<dim3(32, NSIG), 256>>>(y);
}

// round 17
// speedup vs baseline: 1.0583x; 1.0583x over previous
#include <cuda_runtime.h>
#include <math.h>

// EpochedFutureFill: B=256, T=32768, L=32768 -> n_fft = 65536 = 256*256.
// Four-step FFT convolution, register-resident 256-pt warp FFTs (pure shfl).
// R14 = R11 + (a) float2-typed smem tiles (64-bit LDS/STS, halves tile ops),
//             (b) d=1 shfl stage specialized (W=1: no multiply).
#define T_LEN   32768
#define N_FFT   65536
#define NSIG    128
#define SCALE_INV (1.0f / 65536.0f)

__device__ float4 d_scr4[NSIG * N_FFT / 2];  // 64 MB workspace (16B aligned)
__device__ float2 d_Htmp[N_FFT];             // filter intermediate
__device__ float2 d_Hs[N_FFT];               // filter spectrum [p][q] slots
__device__ float2 d_t256g[256];              // W_256^j
__device__ float2 d_WL [N_FFT];              // W_N^{n1*brev(p)}, [n1][p]
__device__ float2 d_WLT[N_FFT];              // same values, [p][n1]

__device__ __forceinline__ float2 cmul(float2 a, float2 b) {
    return make_float2(a.x * b.x - a.y * b.y, a.x * b.y + a.y * b.x);
}
__device__ __forceinline__ float2 cmulc(float2 a, float2 b) {  // a * conj(b)
    return make_float2(a.x * b.x + a.y * b.y, a.y * b.x - a.x * b.y);
}
__device__ __forceinline__ void bfly_f(float2& lo, float2& hi, float2 w) {
    float2 a = lo, b = hi;
    lo = make_float2(a.x + b.x, a.y + b.y);
    hi = cmul(make_float2(a.x - b.x, a.y - b.y), w);
}
__device__ __forceinline__ void bfly_i(float2& lo, float2& hi, float2 w) {
    float2 t = cmulc(hi, w);
    float2 a = lo;
    lo = make_float2(a.x + t.x, a.y + t.y);
    hi = make_float2(a.x - t.x, a.y - t.y);
}

// One-time twiddle build: t256 + both long-twiddle tables.
__global__ void k_init() {
    int idx = blockIdx.x * 256 + threadIdx.x;    // 256 x 256 = 65536
    int n1 = idx >> 8, p = idx & 255;
    int k2 = __brev(p) >> 24;
    float sn, cs;
    sincospif(-(float)(n1 * k2) / 32768.0f, &sn, &cs);
    float2 wv = make_float2(cs, sn);
    d_WL [idx]          = wv;
    d_WLT[p * 256 + n1] = wv;
    if (idx < 256) {
        sincospif(-(float)idx / 128.0f, &sn, &cs);
        d_t256g[idx] = make_float2(cs, sn);
    }
}

// 256-pt forward DIF FFT, warp-register-resident. v[k] = point 32k+lane.
// Natural order in, bit-reversed slot out. d=1 stage: W=1, no multiply.
__device__ __forceinline__ void fft256_reg(float2 v[8],
                                           const float2* __restrict__ t256,
                                           int lane) {
#pragma unroll
    for (int k = 0; k < 4; ++k) bfly_f(v[k], v[k + 4], t256[32 * k + lane]);
    {
        float2 w0 = t256[2 * lane], w1 = t256[64 + 2 * lane];
        bfly_f(v[0], v[2], w0); bfly_f(v[1], v[3], w1);
        bfly_f(v[4], v[6], w0); bfly_f(v[5], v[7], w1);
    }
    {
        float2 w = t256[4 * lane];
        bfly_f(v[0], v[1], w); bfly_f(v[2], v[3], w);
        bfly_f(v[4], v[5], w); bfly_f(v[6], v[7], w);
    }
#pragma unroll
    for (int s = 0; s < 4; ++s) {              // d = 16, 8, 4, 2
        const int d = 16 >> s;
        float2 w = t256[(lane & (d - 1)) * (128 / d)];
        const bool up = (lane & d) != 0;
#pragma unroll
        for (int k = 0; k < 8; ++k) {
            float tr = __shfl_xor_sync(0xffffffffu, v[k].x, d);
            float ti = __shfl_xor_sync(0xffffffffu, v[k].y, d);
            if (up) v[k] = cmul(make_float2(tr - v[k].x, ti - v[k].y), w);
            else    { v[k].x += tr; v[k].y += ti; }
        }
    }
    {   // d=1: W = 1 -> pure add/sub
        const bool up = (lane & 1) != 0;
#pragma unroll
        for (int k = 0; k < 8; ++k) {
            float tr = __shfl_xor_sync(0xffffffffu, v[k].x, 1);
            float ti = __shfl_xor_sync(0xffffffffu, v[k].y, 1);
            v[k] = up ? make_float2(tr - v[k].x, ti - v[k].y)
                      : make_float2(v[k].x + tr, v[k].y + ti);
        }
    }
}

// 256-pt inverse (unnormalized, x256), exact reverse graph.
__device__ __forceinline__ void ifft256_reg(float2 v[8],
                                            const float2* __restrict__ t256,
                                            int lane) {
    {   // d=1: W = 1 -> pure add/sub
        const bool up = (lane & 1) != 0;
#pragma unroll
        for (int k = 0; k < 8; ++k) {
            float tr = __shfl_xor_sync(0xffffffffu, v[k].x, 1);
            float ti = __shfl_xor_sync(0xffffffffu, v[k].y, 1);
            v[k] = up ? make_float2(tr - v[k].x, ti - v[k].y)
                      : make_float2(v[k].x + tr, v[k].y + ti);
        }
    }
#pragma unroll
    for (int s = 1; s < 5; ++s) {              // d = 2, 4, 8, 16
        const int d = 1 << s;
        float2 w = t256[(lane & (d - 1)) * (128 / d)];
        const bool up = (lane & d) != 0;
#pragma unroll
        for (int k = 0; k < 8; ++k) {
            float2 x = v[k];
            if (up) x = cmulc(x, w);
            float tr = __shfl_xor_sync(0xffffffffu, x.x, d);
            float ti = __shfl_xor_sync(0xffffffffu, x.y, d);
            v[k] = up ? make_float2(tr - x.x, ti - x.y)
                      : make_float2(x.x + tr, x.y + ti);
        }
    }
    {
        float2 w = t256[4 * lane];
        bfly_i(v[0], v[1], w); bfly_i(v[2], v[3], w);
        bfly_i(v[4], v[5], w); bfly_i(v[6], v[7], w);
    }
    {
        float2 w0 = t256[2 * lane], w1 = t256[64 + 2 * lane];
        bfly_i(v[0], v[2], w0); bfly_i(v[1], v[3], w1);
        bfly_i(v[4], v[6], w0); bfly_i(v[5], v[7], w1);
    }
#pragma unroll
    for (int k = 0; k < 4; ++k) bfly_i(v[k], v[k + 4], t256[32 * k + lane]);
}

// ---------------------------------------------------------------------------
// Pass 1: FFT over n2, long twiddle (d_WL row), store d_scr [n1][p].
// float2 tile [8][130]: STS.64 banks 16*n1q+4i+2*n2 distinct per half-warp.
// ---------------------------------------------------------------------------
__global__ void __launch_bounds__(256, 3) k_pass1(const float* __restrict__ x) {
    __shared__ float2 st[8][130];
    __shared__ float2 t256[256];
    const int tid = threadIdx.x, sgn = blockIdx.y, n1b = blockIdx.x * 8;
    t256[tid] = d_t256g[tid];

    const float4* __restrict__ xr4 =
        (const float4*)(x + (size_t)(2 * sgn)     * T_LEN);
    const float4* __restrict__ xi4 =
        (const float4*)(x + (size_t)(2 * sgn + 1) * T_LEN);
    {
        int n1q = tid & 1, n2 = tid >> 1;      // n2 in [0,128)
        int g4 = (n1b >> 2) + n1q + 64 * n2;   // float4 index
        float4 a = xr4[g4];                    // re of 4 consecutive n1
        float4 b = xi4[g4];                    // im of same
        st[4*n1q+0][n2] = make_float2(a.x, b.x);
        st[4*n1q+1][n2] = make_float2(a.y, b.y);
        st[4*n1q+2][n2] = make_float2(a.z, b.z);
        st[4*n1q+3][n2] = make_float2(a.w, b.w);
    }
    __syncthreads();

    const int w = tid >> 5, lane = tid & 31;
    float2 v[8];
#pragma unroll
    for (int k = 0; k < 4; ++k) {
        v[k]     = st[w][32 * k + lane];
        v[k + 4] = make_float2(0.f, 0.f);      // zero pad [T, N)
    }
    fft256_reg(v, t256, lane);

    const int n1 = n1b + w;
    const float2* __restrict__ WL = d_WL + (size_t)n1 * 256;
    float2* __restrict__ out =
        (float2*)d_scr4 + (size_t)sgn * N_FFT + (size_t)n1 * 256;
#pragma unroll
    for (int k = 0; k < 8; ++k) {
        int p = 32 * k + lane;
        out[p] = cmul(v[k], WL[p]);            // coalesced
    }
}

// ---------------------------------------------------------------------------
// Pass 2 (fused): fwd FFT over n1, multiply Hs, inverse FFT, un-twiddle.
// float2 tile [8][258]: in-STS banks 8jj+4e+2n1, FFT-LDS 4w+2lane, both
// distinct per half-warp (258*2 = 516 words, 516 mod 32 = 4).
// ---------------------------------------------------------------------------
__global__ void __launch_bounds__(256, 3) k_pass2() {
    __shared__ float2 st[8][258];
    __shared__ float2 t256[256];
    const int tid = threadIdx.x, sgn = blockIdx.y, pb = blockIdx.x * 8;
    t256[tid] = d_t256g[tid];

    float2* __restrict__ base = (float2*)d_scr4 + (size_t)sgn * N_FFT;
#pragma unroll
    for (int it = 0; it < 4; ++it) {
        int idx = tid + it * 256;
        int jj = idx & 3, n1 = idx >> 2;
        float4 t = *(const float4*)&base[(size_t)n1 * 256 + pb + 2 * jj];
        st[2*jj  ][n1] = make_float2(t.x, t.y);
        st[2*jj+1][n1] = make_float2(t.z, t.w);
    }
    __syncthreads();

    const int w = tid >> 5, lane = tid & 31;
    float2 v[8];
#pragma unroll
    for (int k = 0; k < 8; ++k) v[k] = st[w][32 * k + lane];
    __syncthreads();                           // reads done before overwrite

    fft256_reg(v, t256, lane);                 // over n1 -> slots q

    const int p = pb + w;
    const float2* __restrict__ H = d_Hs + (size_t)p * 256;
#pragma unroll
    for (int k = 0; k < 8; ++k) v[k] = cmul(v[k], H[32 * k + lane]);

    ifft256_reg(v, t256, lane);                // -> natural n1

    const float2* __restrict__ WT = d_WLT + (size_t)p * 256;
#pragma unroll
    for (int k = 0; k < 8; ++k) {
        int n1 = 32 * k + lane;
        v[k] = cmulc(v[k], WT[n1]);            // * W_N^{-n1*k2}
    }

#pragma unroll
    for (int k = 0; k < 8; ++k) st[w][32 * k + lane] = v[k];
    __syncthreads();
#pragma unroll
    for (int it = 0; it < 4; ++it) {
        int idx = tid + it * 256;
        int jj = idx & 3, n1 = idx >> 2;
        float2 lo = st[2*jj][n1], hi = st[2*jj+1][n1];
        float4 t;  t.x = lo.x; t.y = lo.y; t.z = hi.x; t.w = hi.y;
        *(float4*)&base[(size_t)n1 * 256 + pb + 2 * jj] = t;
    }
}

// ---------------------------------------------------------------------------
// Pass 3: inverse FFT over k2, scale, transposed float4 store (n2 < 128).
// ---------------------------------------------------------------------------
__global__ void __launch_bounds__(256, 3) k_pass3(float* __restrict__ y) {
    __shared__ float2 st[8][130];
    __shared__ float2 t256[256];
    const int tid = threadIdx.x, sgn = blockIdx.y, n1b = blockIdx.x * 8;
    t256[tid] = d_t256g[tid];

    const int w = tid >> 5, lane = tid & 31;
    const float2* __restrict__ row =
        (float2*)d_scr4 + (size_t)sgn * N_FFT + (size_t)(n1b + w) * 256;
    float2 v[8];
#pragma unroll
    for (int k = 0; k < 8; ++k) v[k] = row[32 * k + lane];   // coalesced
    __syncthreads();                           // t256 ready

    ifft256_reg(v, t256, lane);                // natural n2 = 32k+lane

#pragma unroll
    for (int k = 0; k < 4; ++k)                // only n2 < 128 -> n < T
        st[w][32 * k + lane] = make_float2(v[k].x * SCALE_INV,
                                           v[k].y * SCALE_INV);
    __syncthreads();

    float4* __restrict__ yr4 = (float4*)(y + (size_t)(2 * sgn)     * T_LEN);
    float4* __restrict__ yi4 = (float4*)(y + (size_t)(2 * sgn + 1) * T_LEN);
    {
        int n1q = tid & 1, n2 = tid >> 1;
        int g4 = (n1b >> 2) + n1q + 64 * n2;
        float2 c0 = st[4*n1q+0][n2], c1 = st[4*n1q+1][n2];
        float2 c2 = st[4*n1q+2][n2], c3 = st[4*n1q+3][n2];
        float4 a, b;
        a.x = c0.x; a.y = c1.x; a.z = c2.x; a.w = c3.x;
        b.x = c0.y; b.y = c1.y; b.z = c2.y; b.w = c3.y;
        yr4[g4] = a;
        yi4[g4] = b;
    }
}

// ---------------------------------------------------------------------------
// Filter pass 1: real input -> d_Htmp [n1][p].
// ---------------------------------------------------------------------------
__global__ void __launch_bounds__(256) k_fpass1(const float* __restrict__ filt) {
    __shared__ float  sre[8][132];
    __shared__ float2 t256[256];
    const int tid = threadIdx.x, n1b = blockIdx.x * 8;
    t256[tid] = d_t256g[tid];

#pragma unroll
    for (int it = 0; it < 4; ++it) {
        int idx = tid + it * 256;
        int n1l = idx & 7, n2 = idx >> 3;
        sre[n1l][n2] = filt[n1b + n1l + 256 * n2];   // < 32768 = L
    }
    __syncthreads();

    const int w = tid >> 5, lane = tid & 31;
    float2 v[8];
#pragma unroll
    for (int k = 0; k < 4; ++k) {
        v[k]     = make_float2(sre[w][32 * k + lane], 0.f);
        v[k + 4] = make_float2(0.f, 0.f);
    }
    fft256_reg(v, t256, lane);

    const int n1 = n1b + w;
    const float2* __restrict__ WL = d_WL + (size_t)n1 * 256;
    float2* __restrict__ out = d_Htmp + (size_t)n1 * 256;
#pragma unroll
    for (int k = 0; k < 8; ++k) {
        int p = 32 * k + lane;
        out[p] = cmul(v[k], WL[p]);
    }
}

// ---------------------------------------------------------------------------
// Filter pass 2: fwd FFT over n1 per p; store slots d_Hs[p*256 + q].
// ---------------------------------------------------------------------------
__global__ void __launch_bounds__(256) k_fpass2() {
    __shared__ float2 st[8][258];
    __shared__ float2 t256[256];
    const int tid = threadIdx.x, pb = blockIdx.x * 8;
    t256[tid] = d_t256g[tid];

#pragma unroll
    for (int it = 0; it < 8; ++it) {
        int idx = tid + it * 256;
        int j = idx & 7, n1 = idx >> 3;
        st[j][n1] = d_Htmp[(size_t)n1 * 256 + pb + j];
    }
    __syncthreads();

    const int w = tid >> 5, lane = tid & 31;
    float2 v[8];
#pragma unroll
    for (int k = 0; k < 8; ++k) v[k] = st[w][32 * k + lane];
    fft256_reg(v, t256, lane);

    float2* __restrict__ out = (float2*)d_Hs + (size_t)(pb + w) * 256;
#pragma unroll
    for (int k = 0; k < 8; ++k) out[32 * k + lane] = v[k];
}

// ---------------------------------------------------------------------------
extern "C" void kernel_launch(void* const* d_in, const int* in_sizes, int n_in,
                              void* d_out, int out_size) {
    (void)out_size;
    const float* x    = (const float*)d_in[0];   // (256, 32768) fp32
    const float* filt = (const float*)d_in[1];   // (1, 32768)   fp32
    if (in_sizes && n_in >= 2 && in_sizes[0] == T_LEN) {  // safety: swapped
        x    = (const float*)d_in[1];
        filt = (const float*)d_in[0];
    }
    float* y = (float*)d_out;                    // (256, 32768) fp32

    k_init  <<<256, 256>>>();
    k_fpass1<<<32, 256>>>(filt);
    k_fpass2<<<32, 256>>>();
    k_pass1 <<<dim3(32, NSIG), 256>>>(x);
    k_pass2 <<<dim3(32, NSIG), 256>>>();
    k_pass3 <<<dim3(32, NSIG), 256>>>(y);
}